// round 9
// baseline (speedup 1.0000x reference)
#include <cuda_runtime.h>
#include <cuda_fp16.h>
#include <math_constants.h>
#include <cstdint>

#define B_ 256
#define P_ 196
#define E_ 2048
#define D_ 512
#define A_ 512
#define M_ (B_*P_)   // 50176

// Scratch: att2 [B,A], partial logits [2][M], fp16-transposed Wenc [A,E]
__device__ float  g_att2[B_*A_];
__device__ float  g_attp[2*M_];
__device__ __half g_WhT[A_*E_];

// ---------------------------------------------------------------------------
__device__ __forceinline__ uint32_t smem_u32(const void* p) {
    uint32_t a;
    asm("{ .reg .u64 t; cvta.to.shared.u64 t, %1; cvt.u32.u64 %0, t; }"
        : "=r"(a) : "l"(p));
    return a;
}
__device__ __forceinline__ void cp16(uint32_t saddr, const void* gaddr) {
    asm volatile("cp.async.cg.shared.global [%0], [%1], 16;\n"
                 :: "r"(saddr), "l"(gaddr));
}
__device__ __forceinline__ void ldsm4(uint32_t* r, uint32_t addr) {
    asm volatile("ldmatrix.sync.aligned.m8n8.x4.shared.b16 {%0,%1,%2,%3}, [%4];"
                 : "=r"(r[0]), "=r"(r[1]), "=r"(r[2]), "=r"(r[3]) : "r"(addr));
}
#define MMA_F16(d, a, b)                                               \
    asm volatile(                                                      \
        "mma.sync.aligned.m16n8k16.row.col.f32.f16.f16.f32 "           \
        "{%0,%1,%2,%3}, {%4,%5,%6,%7}, {%8,%9}, {%0,%1,%2,%3};\n"      \
        : "+f"((d)[0]), "+f"((d)[1]), "+f"((d)[2]), "+f"((d)[3])       \
        : "r"((a)[0]), "r"((a)[1]), "r"((a)[2]), "r"((a)[3]),          \
          "r"((b)[0]), "r"((b)[1]))

// ---------------------------------------------------------------------------
// Stage 0: transpose + convert Wenc [E,A] f32 -> g_WhT [A,E] fp16
// ---------------------------------------------------------------------------
__global__ void transpose_kernel(const float* __restrict__ W) {
    __shared__ float tile[32][33];
    const int k0 = blockIdx.x * 32, n0 = blockIdx.y * 32;
    for (int i = threadIdx.y; i < 32; i += 8)
        tile[i][threadIdx.x] = W[(size_t)(k0 + i) * A_ + n0 + threadIdx.x];
    __syncthreads();
    for (int i = threadIdx.y; i < 32; i += 8)
        g_WhT[(size_t)(n0 + i) * E_ + k0 + threadIdx.x] =
            __float2half_rn(tile[threadIdx.x][i]);
}

// ---------------------------------------------------------------------------
// Stage 1: att2[b,a] = decoder_hidden[b,:] @ W_dec[:,a] + b_dec[a]
// ---------------------------------------------------------------------------
__global__ void att2_kernel(const float* __restrict__ dh,
                            const float* __restrict__ Wdec,
                            const float* __restrict__ bdec) {
    __shared__ float sdh[16][D_];
    const int colBase = blockIdx.x * 128;
    const int bBase   = blockIdx.y * 16;
    const int t = threadIdx.x;

    for (int i = t; i < 16 * D_; i += 256) {
        int bb = i / D_, k = i % D_;
        sdh[bb][k] = dh[(bBase + bb) * D_ + k];
    }
    __syncthreads();

    const int col   = colBase + (t & 127);
    const int bhalf = t >> 7;
    float acc[8];
    #pragma unroll
    for (int i = 0; i < 8; i++) acc[i] = 0.0f;

    for (int k = 0; k < D_; k++) {
        float w = Wdec[k * A_ + col];
        #pragma unroll
        for (int i = 0; i < 8; i++)
            acc[i] = fmaf(sdh[bhalf * 8 + i][k], w, acc[i]);
    }
    float bd = bdec[col];
    #pragma unroll
    for (int i = 0; i < 8; i++)
        g_att2[(bBase + bhalf * 8 + i) * A_ + col] = acc[i] + bd;
}

// ---------------------------------------------------------------------------
// Stage 2: fp16 mma.sync GEMM + fused epilogue.
//   BM=64, BN=256, BK=32, 512 threads (16 warps, warp tile 16x64).
//   grid (2, 784): col-half fastest => pairs share enc row-tile in L2.
//   1568 CTAs -> 10.59/SM, makespan 11 (tail 3.8% vs 13.2% at BM=128).
// ---------------------------------------------------------------------------
#define AS 40                        // smem row stride in halves (80 B)
#define KT (E_/32)                   // 64 stages
#define SM_A0 0                      // A buf: 64*80  = 5120 B
#define SM_A1 5120
#define SM_B0 10240                  // B buf: 256*80 = 20480 B
#define SM_B1 30720
#define SM_TOTAL 51200

__global__ __launch_bounds__(512, 1)
void main_gemm_h(const float* __restrict__ enc,
                 const float* __restrict__ benc,
                 const float* __restrict__ wfull) {
    extern __shared__ __align__(128) char smem[];
    const uint32_t sb = smem_u32(smem);
    const int tid  = threadIdx.x;
    const int lane = tid & 31;
    const int warp = tid >> 5;
    const int mw   = warp >> 2;          // 0..3  (m block of 16)
    const int nw   = warp & 3;           // 0..3  (n block of 64)
    const int part    = blockIdx.x;      // 0..1  col half
    const int colBase = part * 256;
    const int rowBase = blockIdx.y * 64;

    const uint32_t aBuf[2] = { sb + SM_A0, sb + SM_A1 };
    const uint32_t bBuf[2] = { sb + SM_B0, sb + SM_B1 };

    // ldmatrix per-thread address offsets (R7-proven formulas, 16-row A tile)
    const uint32_t aOff = (uint32_t)((mw * 16 + (lane & 15)) * 80)
                        + (uint32_t)((lane >> 4) * 16);
    const int bRow0 = nw * 64 + (lane & 7) + ((lane >> 4) & 1) * 8;
    const uint32_t bOff = (uint32_t)(bRow0 * 80)
                        + (uint32_t)(((lane >> 3) & 1) * 16);

    // A loader: 64 rows x 4 quads = 256 chunks; threads 0..255 take one each
    const int ar = tid >> 2, aq = tid & 3;
    const float* aG = enc + (size_t)(rowBase + ar) * E_ + aq * 8;
    const uint32_t aSt = (uint32_t)(ar * 80 + aq * 16);

    // B loader: 256 rows x 4 quads = 1024 chunks / 512 threads = 2 each
    const __half* bG0 = g_WhT + (size_t)(colBase + (tid >> 2)) * E_ + (tid & 3) * 8;
    const __half* bG1 = g_WhT + (size_t)(colBase + 128 + (tid >> 2)) * E_ + (tid & 3) * 8;
    const uint32_t bSt0 = (uint32_t)((tid >> 2) * 80 + (tid & 3) * 16);
    const uint32_t bSt1 = (uint32_t)((128 + (tid >> 2)) * 80 + (tid & 3) * 16);

    auto cvt8 = [](const float* p) -> uint4 {
        float4 f0 = *(const float4*)p;
        float4 f1 = *(const float4*)(p + 4);
        __half2 h0 = __floats2half2_rn(f0.x, f0.y);
        __half2 h1 = __floats2half2_rn(f0.z, f0.w);
        __half2 h2 = __floats2half2_rn(f1.x, f1.y);
        __half2 h3 = __floats2half2_rn(f1.z, f1.w);
        uint4 u;
        u.x = *(uint32_t*)&h0; u.y = *(uint32_t*)&h1;
        u.z = *(uint32_t*)&h2; u.w = *(uint32_t*)&h3;
        return u;
    };
    auto cpB = [&](int s, int k0) {
        cp16(bBuf[s] + bSt0, bG0 + k0);
        cp16(bBuf[s] + bSt1, bG1 + k0);
        asm volatile("cp.async.commit_group;\n" ::: "memory");
    };

    float acc[8][4];
    #pragma unroll
    for (int nj = 0; nj < 8; nj++)
        #pragma unroll
        for (int e = 0; e < 4; e++) acc[nj][e] = 0.0f;

    // prologue: stage 0
    if (tid < 256) *(uint4*)(smem + SM_A0 + aSt) = cvt8(aG);
    cpB(0, 0);

    for (int t = 0; t < KT; t++) {
        const int s = t & 1;
        asm volatile("cp.async.wait_group 0;\n" ::: "memory");
        __syncthreads();

        uint4 aN;
        if (t + 1 < KT) {
            cpB(s ^ 1, (t + 1) * 32);
            if (tid < 256) aN = cvt8(aG + (t + 1) * 32);
        }

        const uint32_t aB = aBuf[s], bB = bBuf[s];
        #pragma unroll
        for (int kk = 0; kk < 2; kk++) {
            uint32_t af[4];
            ldsm4(af, aB + aOff + kk * 32);
            uint32_t bf[8][2];
            #pragma unroll
            for (int p = 0; p < 4; p++) {
                uint32_t r4[4];
                ldsm4(r4, bB + bOff + p * 1280 + kk * 32);  // +16 rows * 80B
                bf[2*p][0]   = r4[0]; bf[2*p][1]   = r4[1];
                bf[2*p+1][0] = r4[2]; bf[2*p+1][1] = r4[3];
            }
            #pragma unroll
            for (int nj = 0; nj < 8; nj++)
                MMA_F16(acc[nj], af, bf[nj]);
        }

        if (t + 1 < KT && tid < 256)
            *(uint4*)(smem + (SM_A0 + (s ^ 1) * 5120) + aSt) = aN;
    }

    // ---- fused epilogue: relu(att1 + benc + att2) . wfull, per-row sums ----
    __syncthreads();                 // reuse smem
    float* sa2 = (float*)smem;       // [2][256]: benc + att2 for 2 local batches
    float* sw  = (float*)smem + 512; // [256]
    float* red = (float*)smem + 768; // [64][5]
    const int b0 = rowBase / P_;
    const int boundary = (b0 + 1) * P_ - rowBase;   // local row where batch++

    {
        int bb = b0 + (tid >> 8); if (bb > B_ - 1) bb = B_ - 1;
        int c = tid & 255;
        sa2[tid] = benc[colBase + c] + g_att2[bb * A_ + colBase + c];
    }
    if (tid < 256) sw[tid] = wfull[colBase + tid];
    __syncthreads();

    const int c0l = nw * 64 + 2 * (lane & 3);
    #pragma unroll
    for (int h = 0; h < 2; h++) {
        const int rl = mw * 16 + h * 8 + (lane >> 2);
        const float* a2p = sa2 + ((rl >= boundary) ? 256 : 0);
        float s = 0.0f;
        #pragma unroll
        for (int nj = 0; nj < 8; nj++) {
            const int c = c0l + nj * 8;
            float v0 = acc[nj][h * 2 + 0] + a2p[c];
            float v1 = acc[nj][h * 2 + 1] + a2p[c + 1];
            s = fmaf(fmaxf(v0, 0.0f), sw[c], s);
            s = fmaf(fmaxf(v1, 0.0f), sw[c + 1], s);
        }
        s += __shfl_xor_sync(0xFFFFFFFFu, s, 1);
        s += __shfl_xor_sync(0xFFFFFFFFu, s, 2);
        if ((lane & 3) == 0) red[rl * 5 + nw] = s;
    }
    __syncthreads();
    if (tid < 64) {
        float s = red[tid * 5 + 0] + red[tid * 5 + 1]
                + red[tid * 5 + 2] + red[tid * 5 + 3];
        g_attp[part * M_ + rowBase + tid] = s;
    }
}

// ---------------------------------------------------------------------------
// Stage 3: softmax over P=196 per batch (sums the two col-half partials)
// ---------------------------------------------------------------------------
__global__ void softmax_kernel(float* __restrict__ alpha_out) {
    __shared__ float sdata[256];
    const int b = blockIdx.x;
    const int t = threadIdx.x;

    float v = -CUDART_INF_F;
    if (t < P_) {
        int r = b * P_ + t;
        v = g_attp[r] + g_attp[M_ + r];
    }
    sdata[t] = v;
    __syncthreads();
    for (int s = 128; s > 0; s >>= 1) {
        if (t < s) sdata[t] = fmaxf(sdata[t], sdata[t + s]);
        __syncthreads();
    }
    float m = sdata[0];
    __syncthreads();

    float e = (t < P_) ? expf(v - m) : 0.0f;
    sdata[t] = e;
    __syncthreads();
    for (int s = 128; s > 0; s >>= 1) {
        if (t < s) sdata[t] += sdata[t + s];
        __syncthreads();
    }
    float inv = 1.0f / sdata[0];
    if (t < P_) alpha_out[b * P_ + t] = e * inv;
}

// ---------------------------------------------------------------------------
// Stage 4: awe[b,e] = sum_p enc[b,p,e] * alpha[b,p]
// ---------------------------------------------------------------------------
__global__ void awe_kernel(const float* __restrict__ enc,
                           const float* __restrict__ alpha,
                           float* __restrict__ awe) {
    __shared__ float sa[P_];
    const int b = blockIdx.y;
    const int e = blockIdx.x * 256 + threadIdx.x;
    for (int i = threadIdx.x; i < P_; i += 256)
        sa[i] = alpha[b * P_ + i];
    __syncthreads();

    const float* base = enc + (size_t)b * P_ * E_ + e;
    float acc = 0.0f;
    #pragma unroll 4
    for (int p = 0; p < P_; p++)
        acc = fmaf(base[(size_t)p * E_], sa[p], acc);
    awe[b * E_ + e] = acc;
}

// ---------------------------------------------------------------------------
extern "C" void kernel_launch(void* const* d_in, const int* in_sizes, int n_in,
                              void* d_out, int out_size) {
    const float* enc   = (const float*)d_in[0];
    const float* dh    = (const float*)d_in[1];
    const float* Wenc  = (const float*)d_in[2];
    const float* benc  = (const float*)d_in[3];
    const float* Wdec  = (const float*)d_in[4];
    const float* bdec  = (const float*)d_in[5];
    const float* wfull = (const float*)d_in[6];
    // d_in[7] = b_full: softmax-invariant, dropped.

    float* awe   = (float*)d_out;
    float* alpha = (float*)d_out + (size_t)B_ * E_;

    static int smem_set = 0;
    if (!smem_set) {
        cudaFuncSetAttribute(main_gemm_h,
                             cudaFuncAttributeMaxDynamicSharedMemorySize,
                             SM_TOTAL);
        smem_set = 1;
    }

    transpose_kernel<<<dim3(E_ / 32, A_ / 32), dim3(32, 8)>>>(Wenc);
    att2_kernel<<<dim3(A_ / 128, B_ / 16), 256>>>(dh, Wdec, bdec);
    main_gemm_h<<<dim3(2, M_ / 64), 512, SM_TOTAL>>>(enc, benc, wfull);
    softmax_kernel<<<B_, 256>>>(alpha);
    awe_kernel<<<dim3(E_ / 256, B_), 256>>>(enc, alpha, awe);
}

// round 10
// speedup vs baseline: 1.2567x; 1.2567x over previous
#include <cuda_runtime.h>
#include <cuda_fp16.h>
#include <math_constants.h>
#include <cstdint>

#define B_ 256
#define P_ 196
#define E_ 2048
#define D_ 512
#define A_ 512
#define M_ (B_*P_)   // 50176

// Scratch: att2 [B,A], partial logits [2][M], fp16 Wenc^T [A,E], fp16 enc [M,E]
__device__ float  g_att2[B_*A_];
__device__ float  g_attp[2*M_];
__device__ __half g_WhT[A_*E_];
__device__ __align__(16) __half g_enc16[(size_t)M_*E_];

// ---------------------------------------------------------------------------
__device__ __forceinline__ uint32_t smem_u32(const void* p) {
    uint32_t a;
    asm("{ .reg .u64 t; cvta.to.shared.u64 t, %1; cvt.u32.u64 %0, t; }"
        : "=r"(a) : "l"(p));
    return a;
}
__device__ __forceinline__ void cp16(uint32_t saddr, const void* gaddr) {
    asm volatile("cp.async.cg.shared.global [%0], [%1], 16;\n"
                 :: "r"(saddr), "l"(gaddr));
}
__device__ __forceinline__ void ldsm4(uint32_t* r, uint32_t addr) {
    asm volatile("ldmatrix.sync.aligned.m8n8.x4.shared.b16 {%0,%1,%2,%3}, [%4];"
                 : "=r"(r[0]), "=r"(r[1]), "=r"(r[2]), "=r"(r[3]) : "r"(addr));
}
#define MMA_F16(d, a, b)                                               \
    asm volatile(                                                      \
        "mma.sync.aligned.m16n8k16.row.col.f32.f16.f16.f32 "           \
        "{%0,%1,%2,%3}, {%4,%5,%6,%7}, {%8,%9}, {%0,%1,%2,%3};\n"      \
        : "+f"((d)[0]), "+f"((d)[1]), "+f"((d)[2]), "+f"((d)[3])       \
        : "r"((a)[0]), "r"((a)[1]), "r"((a)[2]), "r"((a)[3]),          \
          "r"((b)[0]), "r"((b)[1]))

// ---------------------------------------------------------------------------
// Stage 0: transpose + convert Wenc [E,A] f32 -> g_WhT [A,E] fp16
// ---------------------------------------------------------------------------
__global__ void transpose_kernel(const float* __restrict__ W) {
    __shared__ float tile[32][33];
    const int k0 = blockIdx.x * 32, n0 = blockIdx.y * 32;
    for (int i = threadIdx.y; i < 32; i += 8)
        tile[i][threadIdx.x] = W[(size_t)(k0 + i) * A_ + n0 + threadIdx.x];
    __syncthreads();
    for (int i = threadIdx.y; i < 32; i += 8)
        g_WhT[(size_t)(n0 + i) * E_ + k0 + threadIdx.x] =
            __float2half_rn(tile[threadIdx.x][i]);
}

// ---------------------------------------------------------------------------
// Stage 1: att2[b,a] = decoder_hidden[b,:] @ W_dec[:,a] + b_dec[a]
// ---------------------------------------------------------------------------
__global__ void att2_kernel(const float* __restrict__ dh,
                            const float* __restrict__ Wdec,
                            const float* __restrict__ bdec) {
    __shared__ float sdh[16][D_];
    const int colBase = blockIdx.x * 128;
    const int bBase   = blockIdx.y * 16;
    const int t = threadIdx.x;

    for (int i = t; i < 16 * D_; i += 256) {
        int bb = i / D_, k = i % D_;
        sdh[bb][k] = dh[(bBase + bb) * D_ + k];
    }
    __syncthreads();

    const int col   = colBase + (t & 127);
    const int bhalf = t >> 7;
    float acc[8];
    #pragma unroll
    for (int i = 0; i < 8; i++) acc[i] = 0.0f;

    for (int k = 0; k < D_; k++) {
        float w = Wdec[k * A_ + col];
        #pragma unroll
        for (int i = 0; i < 8; i++)
            acc[i] = fmaf(sdh[bhalf * 8 + i][k], w, acc[i]);
    }
    float bd = bdec[col];
    #pragma unroll
    for (int i = 0; i < 8; i++)
        g_att2[(bBase + bhalf * 8 + i) * A_ + col] = acc[i] + bd;
}

// ---------------------------------------------------------------------------
// Stage 2: fp16 mma.sync GEMM + fused epilogue (exact R7 machinery).
//   BM=128, BN=256, BK=32, 512 threads (16 warps, warp tile 32x64).
//   grid (2, 392): col-half fastest -> pairs share enc row-tile in L2.
//   part 0 CTAs additionally write converted A tiles to g_enc16 [M,E].
// ---------------------------------------------------------------------------
#define AS 40                        // smem row stride in halves (80 B)
#define KT (E_/32)                   // 64 stages
#define SM_A0 0
#define SM_A1 10240
#define SM_B0 20480
#define SM_B1 40960
#define SM_TOTAL 61440

__global__ __launch_bounds__(512, 1)
void main_gemm_h(const float* __restrict__ enc,
                 const float* __restrict__ benc,
                 const float* __restrict__ wfull) {
    extern __shared__ __align__(128) char smem[];
    const uint32_t sb = smem_u32(smem);
    const int tid  = threadIdx.x;
    const int lane = tid & 31;
    const int warp = tid >> 5;
    const int mw   = warp >> 2;          // 0..3  (m block of 32)
    const int nw   = warp & 3;           // 0..3  (n block of 64)
    const int part    = blockIdx.x;      // 0..1  col half (fastest)
    const int colBase = part * 256;
    const int rowBase = blockIdx.y * 128;

    const uint32_t aBuf[2] = { sb + SM_A0, sb + SM_A1 };
    const uint32_t bBuf[2] = { sb + SM_B0, sb + SM_B1 };

    // ldmatrix per-thread address offsets (R7-proven)
    const uint32_t aOff = (uint32_t)((mw * 32 + (lane & 15)) * AS * 2)
                        + (uint32_t)((lane >> 4) * 16);
    const int bRow = nw * 64 + (lane & 7) + ((lane >> 4) & 1) * 8;
    const uint32_t bOff = (uint32_t)(bRow * AS * 2)
                        + (uint32_t)(((lane >> 3) & 1) * 16);

    // A loader: 512 chunks (128 rows x 4 quads of 8 floats), 1 per thread
    const int am = tid >> 2;
    const int ac = tid & 3;
    const float* aG = enc + (size_t)(rowBase + am) * E_ + ac * 8;
    __half* aE = g_enc16 + (size_t)(rowBase + am) * E_ + ac * 8;
    const uint32_t aSt = (uint32_t)(am * AS * 2 + ac * 16);

    // B loader: 1024 chunks / 512 threads = 2 each
    const __half* bG0 = g_WhT + (size_t)(colBase + (tid >> 2)) * E_ + (tid & 3) * 8;
    const __half* bG1 = g_WhT + (size_t)(colBase + ((tid + 512) >> 2)) * E_ + (tid & 3) * 8;
    const uint32_t bSt0 = (uint32_t)((tid >> 2) * AS * 2 + (tid & 3) * 16);
    const uint32_t bSt1 = (uint32_t)(((tid + 512) >> 2) * AS * 2 + (tid & 3) * 16);

    auto ldgA = [&](int k0) -> uint4 {
        float4 f0 = *(const float4*)(aG + k0);
        float4 f1 = *(const float4*)(aG + k0 + 4);
        __half2 h0 = __floats2half2_rn(f0.x, f0.y);
        __half2 h1 = __floats2half2_rn(f0.z, f0.w);
        __half2 h2 = __floats2half2_rn(f1.x, f1.y);
        __half2 h3 = __floats2half2_rn(f1.z, f1.w);
        uint4 u;
        u.x = *(uint32_t*)&h0; u.y = *(uint32_t*)&h1;
        u.z = *(uint32_t*)&h2; u.w = *(uint32_t*)&h3;
        if (part == 0) *(uint4*)(aE + k0) = u;   // fp16 side product for awe
        return u;
    };
    auto cpB = [&](int s, int k0) {
        cp16(bBuf[s] + bSt0, bG0 + k0);
        cp16(bBuf[s] + bSt1, bG1 + k0);
        asm volatile("cp.async.commit_group;\n" ::: "memory");
    };

    float acc[2][8][4];
    #pragma unroll
    for (int mi = 0; mi < 2; mi++)
        #pragma unroll
        for (int nj = 0; nj < 8; nj++)
            #pragma unroll
            for (int e = 0; e < 4; e++) acc[mi][nj][e] = 0.0f;

    // prologue: stage 0
    {
        uint4 a0 = ldgA(0);
        *(uint4*)(smem + SM_A0 + aSt) = a0;
        cpB(0, 0);
    }

    for (int t = 0; t < KT; t++) {
        const int s = t & 1;
        asm volatile("cp.async.wait_group 0;\n" ::: "memory");
        __syncthreads();

        uint4 aNext;
        if (t + 1 < KT) {
            cpB(s ^ 1, (t + 1) * 32);
            aNext = ldgA((t + 1) * 32);
        }

        const uint32_t aB = aBuf[s], bB = bBuf[s];
        #pragma unroll
        for (int kk = 0; kk < 2; kk++) {
            uint32_t af[2][4];
            ldsm4(af[0], aB + aOff + kk * 32);
            ldsm4(af[1], aB + aOff + 1280 + kk * 32);   // +16 rows * 80B
            uint32_t bf[8][2];
            #pragma unroll
            for (int p = 0; p < 4; p++) {
                uint32_t r4[4];
                ldsm4(r4, bB + bOff + p * 1280 + kk * 32);
                bf[2*p][0]   = r4[0]; bf[2*p][1]   = r4[1];
                bf[2*p+1][0] = r4[2]; bf[2*p+1][1] = r4[3];
            }
            #pragma unroll
            for (int mi = 0; mi < 2; mi++)
                #pragma unroll
                for (int nj = 0; nj < 8; nj++)
                    MMA_F16(acc[mi][nj], af[mi], bf[nj]);
        }

        if (t + 1 < KT)
            *(uint4*)(smem + (SM_A0 + (s ^ 1) * 10240) + aSt) = aNext;
    }

    // ---- fused epilogue: relu(att1 + benc + att2) . wfull, per-row sums ----
    __syncthreads();                 // reuse smem
    float* sa2 = (float*)smem;       // [2][256]: benc + att2 for 2 local batches
    float* sw  = (float*)smem + 512; // [256]
    float* red = (float*)smem + 768; // [128][5]
    const int b0 = rowBase / P_;
    const int boundary = (b0 + 1) * P_ - rowBase;   // local row where batch++

    {
        int bb = b0 + (tid >> 8); if (bb > B_ - 1) bb = B_ - 1;
        int c = tid & 255;
        sa2[tid] = benc[colBase + c] + g_att2[bb * A_ + colBase + c];
    }
    if (tid < 256) sw[tid] = wfull[colBase + tid];
    __syncthreads();

    const int c0l = nw * 64 + 2 * (lane & 3);
    #pragma unroll
    for (int mi = 0; mi < 2; mi++) {
        #pragma unroll
        for (int h = 0; h < 2; h++) {
            const int rl = mw * 32 + mi * 16 + h * 8 + (lane >> 2);
            const float* a2p = sa2 + ((rl >= boundary) ? 256 : 0);
            float s = 0.0f;
            #pragma unroll
            for (int nj = 0; nj < 8; nj++) {
                const int c = c0l + nj * 8;
                float v0 = acc[mi][nj][h * 2 + 0] + a2p[c];
                float v1 = acc[mi][nj][h * 2 + 1] + a2p[c + 1];
                s = fmaf(fmaxf(v0, 0.0f), sw[c], s);
                s = fmaf(fmaxf(v1, 0.0f), sw[c + 1], s);
            }
            s += __shfl_xor_sync(0xFFFFFFFFu, s, 1);
            s += __shfl_xor_sync(0xFFFFFFFFu, s, 2);
            if ((lane & 3) == 0) red[rl * 5 + nw] = s;
        }
    }
    __syncthreads();
    if (tid < 128) {
        g_attp[part * M_ + rowBase + tid] =
            red[tid * 5 + 0] + red[tid * 5 + 1]
          + red[tid * 5 + 2] + red[tid * 5 + 3];
    }
}

// ---------------------------------------------------------------------------
// Stage 3: softmax over P=196 per batch (sums the two col-half partials)
// ---------------------------------------------------------------------------
__global__ void softmax_kernel(float* __restrict__ alpha_out) {
    __shared__ float sdata[256];
    const int b = blockIdx.x;
    const int t = threadIdx.x;

    float v = -CUDART_INF_F;
    if (t < P_) {
        int r = b * P_ + t;
        v = g_attp[r] + g_attp[M_ + r];
    }
    sdata[t] = v;
    __syncthreads();
    for (int s = 128; s > 0; s >>= 1) {
        if (t < s) sdata[t] = fmaxf(sdata[t], sdata[t + s]);
        __syncthreads();
    }
    float m = sdata[0];
    __syncthreads();

    float e = (t < P_) ? expf(v - m) : 0.0f;
    sdata[t] = e;
    __syncthreads();
    for (int s = 128; s > 0; s >>= 1) {
        if (t < s) sdata[t] += sdata[t + s];
        __syncthreads();
    }
    float inv = 1.0f / sdata[0];
    if (t < P_) alpha_out[b * P_ + t] = e * inv;
}

// ---------------------------------------------------------------------------
// Stage 4: awe[b,e] = sum_p enc16[b,p,e] * alpha[b,p]  (fp16 reads, f32 acc)
// grid (E/512, B), 256 threads; each thread owns one __half2 column pair
// ---------------------------------------------------------------------------
__global__ void awe_kernel(const float* __restrict__ alpha,
                           float* __restrict__ awe) {
    __shared__ float sa[P_];
    const int b  = blockIdx.y;
    const int e2 = blockIdx.x * 256 + threadIdx.x;   // half2 index, 0..1023
    for (int i = threadIdx.x; i < P_; i += 256)
        sa[i] = alpha[b * P_ + i];
    __syncthreads();

    const __half2* base = (const __half2*)(g_enc16 + (size_t)b * P_ * E_) + e2;
    float ax = 0.0f, ay = 0.0f;
    #pragma unroll 4
    for (int p = 0; p < P_; p++) {
        float2 f = __half22float2(base[(size_t)p * (E_ / 2)]);
        float w = sa[p];
        ax = fmaf(f.x, w, ax);
        ay = fmaf(f.y, w, ay);
    }
    float2 r; r.x = ax; r.y = ay;
    *(float2*)(awe + (size_t)b * E_ + 2 * e2) = r;
}

// ---------------------------------------------------------------------------
extern "C" void kernel_launch(void* const* d_in, const int* in_sizes, int n_in,
                              void* d_out, int out_size) {
    const float* enc   = (const float*)d_in[0];
    const float* dh    = (const float*)d_in[1];
    const float* Wenc  = (const float*)d_in[2];
    const float* benc  = (const float*)d_in[3];
    const float* Wdec  = (const float*)d_in[4];
    const float* bdec  = (const float*)d_in[5];
    const float* wfull = (const float*)d_in[6];
    // d_in[7] = b_full: softmax-invariant, dropped.

    float* awe   = (float*)d_out;
    float* alpha = (float*)d_out + (size_t)B_ * E_;

    static int smem_set = 0;
    if (!smem_set) {
        cudaFuncSetAttribute(main_gemm_h,
                             cudaFuncAttributeMaxDynamicSharedMemorySize,
                             SM_TOTAL);
        smem_set = 1;
    }

    transpose_kernel<<<dim3(E_ / 32, A_ / 32), dim3(32, 8)>>>(Wenc);
    att2_kernel<<<dim3(A_ / 128, B_ / 16), 256>>>(dh, Wdec, bdec);
    main_gemm_h<<<dim3(2, M_ / 128), 512, SM_TOTAL>>>(enc, benc, wfull);
    softmax_kernel<<<B_, 256>>>(alpha);
    awe_kernel<<<dim3(E_ / 512, B_), 256>>>(alpha, awe);
}

// round 11
// speedup vs baseline: 1.3275x; 1.0563x over previous
#include <cuda_runtime.h>
#include <cuda_fp16.h>
#include <math_constants.h>
#include <cstdint>

#define B_ 256
#define P_ 196
#define E_ 2048
#define D_ 512
#define A_ 512
#define M_ (B_*P_)   // 50176

// Scratch: att2 [B,A], partial logits [2][M], fp16-transposed Wenc [A,E]
__device__ float  g_att2[B_*A_];
__device__ float  g_attp[2*M_];
__device__ __half g_WhT[A_*E_];

// ---------------------------------------------------------------------------
__device__ __forceinline__ uint32_t smem_u32(const void* p) {
    uint32_t a;
    asm("{ .reg .u64 t; cvta.to.shared.u64 t, %1; cvt.u32.u64 %0, t; }"
        : "=r"(a) : "l"(p));
    return a;
}
__device__ __forceinline__ void cp16(uint32_t saddr, const void* gaddr) {
    asm volatile("cp.async.cg.shared.global [%0], [%1], 16;\n"
                 :: "r"(saddr), "l"(gaddr));
}
__device__ __forceinline__ void ldsm4(uint32_t* r, uint32_t addr) {
    asm volatile("ldmatrix.sync.aligned.m8n8.x4.shared.b16 {%0,%1,%2,%3}, [%4];"
                 : "=r"(r[0]), "=r"(r[1]), "=r"(r[2]), "=r"(r[3]) : "r"(addr));
}
#define MMA_F16(d, a, b)                                               \
    asm volatile(                                                      \
        "mma.sync.aligned.m16n8k16.row.col.f32.f16.f16.f32 "           \
        "{%0,%1,%2,%3}, {%4,%5,%6,%7}, {%8,%9}, {%0,%1,%2,%3};\n"      \
        : "+f"((d)[0]), "+f"((d)[1]), "+f"((d)[2]), "+f"((d)[3])       \
        : "r"((a)[0]), "r"((a)[1]), "r"((a)[2]), "r"((a)[3]),          \
          "r"((b)[0]), "r"((b)[1]))

// ---------------------------------------------------------------------------
// Stage 0: transpose + convert Wenc [E,A] f32 -> g_WhT [A,E] fp16
// ---------------------------------------------------------------------------
__global__ void transpose_kernel(const float* __restrict__ W) {
    __shared__ float tile[32][33];
    const int k0 = blockIdx.x * 32, n0 = blockIdx.y * 32;
    for (int i = threadIdx.y; i < 32; i += 8)
        tile[i][threadIdx.x] = W[(size_t)(k0 + i) * A_ + n0 + threadIdx.x];
    __syncthreads();
    for (int i = threadIdx.y; i < 32; i += 8)
        g_WhT[(size_t)(n0 + i) * E_ + k0 + threadIdx.x] =
            __float2half_rn(tile[threadIdx.x][i]);
}

// ---------------------------------------------------------------------------
// Stage 1: att2[b,a] = decoder_hidden[b,:] @ W_dec[:,a] + b_dec[a]
// ---------------------------------------------------------------------------
__global__ void att2_kernel(const float* __restrict__ dh,
                            const float* __restrict__ Wdec,
                            const float* __restrict__ bdec) {
    __shared__ float sdh[16][D_];
    const int colBase = blockIdx.x * 128;
    const int bBase   = blockIdx.y * 16;
    const int t = threadIdx.x;

    for (int i = t; i < 16 * D_; i += 256) {
        int bb = i / D_, k = i % D_;
        sdh[bb][k] = dh[(bBase + bb) * D_ + k];
    }
    __syncthreads();

    const int col   = colBase + (t & 127);
    const int bhalf = t >> 7;
    float acc[8];
    #pragma unroll
    for (int i = 0; i < 8; i++) acc[i] = 0.0f;

    for (int k = 0; k < D_; k++) {
        float w = Wdec[k * A_ + col];
        #pragma unroll
        for (int i = 0; i < 8; i++)
            acc[i] = fmaf(sdh[bhalf * 8 + i][k], w, acc[i]);
    }
    float bd = bdec[col];
    #pragma unroll
    for (int i = 0; i < 8; i++)
        g_att2[(bBase + bhalf * 8 + i) * A_ + col] = acc[i] + bd;
}

// ---------------------------------------------------------------------------
// Stage 2: fp16 mma.sync GEMM + fused epilogue (R7 machinery, BK=64).
//   BM=128, BN=256, BK=64, 512 threads (16 warps, warp tile 32x64).
//   32 stages: half the barrier/refill bubbles of the BK=32 version.
//   smem row stride 144B (72 halves): ldmatrix bank-conflict-free.
// ---------------------------------------------------------------------------
#define ASB 144                      // smem row stride in bytes
#define KT (E_/64)                   // 32 stages
#define SM_A0 0                      // A buf: 128*144 = 18432 B
#define SM_A1 18432
#define SM_B0 36864                  // B buf: 256*144 = 36864 B
#define SM_B1 73728
#define SM_TOTAL 110592

__global__ __launch_bounds__(512, 1)
void main_gemm_h(const float* __restrict__ enc,
                 const float* __restrict__ benc,
                 const float* __restrict__ wfull) {
    extern __shared__ __align__(128) char smem[];
    const uint32_t sb = smem_u32(smem);
    const int tid  = threadIdx.x;
    const int lane = tid & 31;
    const int warp = tid >> 5;
    const int mw   = warp >> 2;          // 0..3  (m block of 32)
    const int nw   = warp & 3;           // 0..3  (n block of 64)
    const int rowBase = blockIdx.x * 128;
    const int colBase = blockIdx.y * 256;
    const int part    = blockIdx.y;

    const uint32_t aBuf[2] = { sb + SM_A0, sb + SM_A1 };
    const uint32_t bBuf[2] = { sb + SM_B0, sb + SM_B1 };

    // ldmatrix per-thread address offsets (R7 formulas, stride 144B)
    const uint32_t aOff = (uint32_t)((mw * 32 + (lane & 15)) * ASB)
                        + (uint32_t)((lane >> 4) * 16);
    const int bRow = nw * 64 + (lane & 7) + ((lane >> 4) & 1) * 8;
    const uint32_t bOff = (uint32_t)(bRow * ASB)
                        + (uint32_t)(((lane >> 3) & 1) * 16);

    // A loader: 128 rows x 8 chunks(16B fp16 = 8 floats) = 1024 / 512 thr = 2
    const int ar0 = tid >> 3,        aq0 = tid & 7;
    const int ar1 = 64 + (tid >> 3), aq1 = tid & 7;
    const float* aG0 = enc + (size_t)(rowBase + ar0) * E_ + aq0 * 8;
    const float* aG1 = enc + (size_t)(rowBase + ar1) * E_ + aq1 * 8;
    const uint32_t aSt0 = (uint32_t)(ar0 * ASB + aq0 * 16);
    const uint32_t aSt1 = (uint32_t)(ar1 * ASB + aq1 * 16);

    // B loader: 256 rows x 8 chunks = 2048 / 512 thr = 4 each
    const int br = tid >> 3, bq = tid & 7;
    const __half* bG = g_WhT + (size_t)(colBase + br) * E_ + bq * 8;
    const uint32_t bSt = (uint32_t)(br * ASB + bq * 16);

    auto cvt8 = [](const float* p) -> uint4 {
        float4 f0 = *(const float4*)p;
        float4 f1 = *(const float4*)(p + 4);
        __half2 h0 = __floats2half2_rn(f0.x, f0.y);
        __half2 h1 = __floats2half2_rn(f0.z, f0.w);
        __half2 h2 = __floats2half2_rn(f1.x, f1.y);
        __half2 h3 = __floats2half2_rn(f1.z, f1.w);
        uint4 u;
        u.x = *(uint32_t*)&h0; u.y = *(uint32_t*)&h1;
        u.z = *(uint32_t*)&h2; u.w = *(uint32_t*)&h3;
        return u;
    };
    auto cpB = [&](int s, int k0) {
        #pragma unroll
        for (int i = 0; i < 4; i++)   // 4 x 64 rows
            cp16(bBuf[s] + bSt + (uint32_t)(i * 64 * ASB),
                 bG + k0 + (size_t)(i * 64) * E_);
        asm volatile("cp.async.commit_group;\n" ::: "memory");
    };

    float acc[2][8][4];
    #pragma unroll
    for (int mi = 0; mi < 2; mi++)
        #pragma unroll
        for (int nj = 0; nj < 8; nj++)
            #pragma unroll
            for (int e = 0; e < 4; e++) acc[mi][nj][e] = 0.0f;

    // prologue: stage 0
    {
        *(uint4*)(smem + SM_A0 + aSt0) = cvt8(aG0);
        *(uint4*)(smem + SM_A0 + aSt1) = cvt8(aG1);
        cpB(0, 0);
    }

    for (int t = 0; t < KT; t++) {
        const int s = t & 1;
        asm volatile("cp.async.wait_group 0;\n" ::: "memory");
        __syncthreads();

        uint4 aN0, aN1;
        if (t + 1 < KT) {
            cpB(s ^ 1, (t + 1) * 64);
            aN0 = cvt8(aG0 + (t + 1) * 64);
            aN1 = cvt8(aG1 + (t + 1) * 64);
        }

        const uint32_t aB = aBuf[s], bB = bBuf[s];
        #pragma unroll
        for (int kk = 0; kk < 4; kk++) {
            uint32_t af[2][4];
            ldsm4(af[0], aB + aOff + kk * 32);
            ldsm4(af[1], aB + aOff + 16 * ASB + kk * 32);
            uint32_t bf[8][2];
            #pragma unroll
            for (int p = 0; p < 4; p++) {
                uint32_t r4[4];
                ldsm4(r4, bB + bOff + p * 16 * ASB + kk * 32);
                bf[2*p][0]   = r4[0]; bf[2*p][1]   = r4[1];
                bf[2*p+1][0] = r4[2]; bf[2*p+1][1] = r4[3];
            }
            #pragma unroll
            for (int mi = 0; mi < 2; mi++)
                #pragma unroll
                for (int nj = 0; nj < 8; nj++)
                    MMA_F16(acc[mi][nj], af[mi], bf[nj]);
        }

        if (t + 1 < KT) {
            char* dst = smem + (s ? SM_A0 : SM_A1);
            *(uint4*)(dst + aSt0) = aN0;
            *(uint4*)(dst + aSt1) = aN1;
        }
    }

    // ---- fused epilogue: relu(att1 + benc + att2) . wfull, per-row sums ----
    __syncthreads();                 // reuse smem
    float* sa2 = (float*)smem;       // [2][256]: benc + att2 for 2 local batches
    float* sw  = (float*)smem + 512; // [256]
    float* red = (float*)smem + 768; // [128][5]
    const int b0 = rowBase / P_;
    const int boundary = (b0 + 1) * P_ - rowBase;   // local row where batch++

    {
        int bb = b0 + (tid >> 8); if (bb > B_ - 1) bb = B_ - 1;
        int c = tid & 255;
        sa2[tid] = benc[colBase + c] + g_att2[bb * A_ + colBase + c];
    }
    if (tid < 256) sw[tid] = wfull[colBase + tid];
    __syncthreads();

    const int c0l = nw * 64 + 2 * (lane & 3);
    #pragma unroll
    for (int mi = 0; mi < 2; mi++) {
        #pragma unroll
        for (int h = 0; h < 2; h++) {
            const int rl = mw * 32 + mi * 16 + h * 8 + (lane >> 2);
            const float* a2p = sa2 + ((rl >= boundary) ? 256 : 0);
            float s = 0.0f;
            #pragma unroll
            for (int nj = 0; nj < 8; nj++) {
                const int c = c0l + nj * 8;
                float v0 = acc[mi][nj][h * 2 + 0] + a2p[c];
                float v1 = acc[mi][nj][h * 2 + 1] + a2p[c + 1];
                s = fmaf(fmaxf(v0, 0.0f), sw[c], s);
                s = fmaf(fmaxf(v1, 0.0f), sw[c + 1], s);
            }
            s += __shfl_xor_sync(0xFFFFFFFFu, s, 1);
            s += __shfl_xor_sync(0xFFFFFFFFu, s, 2);
            if ((lane & 3) == 0) red[rl * 5 + nw] = s;
        }
    }
    __syncthreads();
    if (tid < 128) {
        g_attp[part * M_ + rowBase + tid] =
            red[tid * 5 + 0] + red[tid * 5 + 1]
          + red[tid * 5 + 2] + red[tid * 5 + 3];
    }
}

// ---------------------------------------------------------------------------
// Stage 3: softmax over P=196 per batch (sums the two col-half partials)
// ---------------------------------------------------------------------------
__global__ void softmax_kernel(float* __restrict__ alpha_out) {
    __shared__ float sdata[256];
    const int b = blockIdx.x;
    const int t = threadIdx.x;

    float v = -CUDART_INF_F;
    if (t < P_) {
        int r = b * P_ + t;
        v = g_attp[r] + g_attp[M_ + r];
    }
    sdata[t] = v;
    __syncthreads();
    for (int s = 128; s > 0; s >>= 1) {
        if (t < s) sdata[t] = fmaxf(sdata[t], sdata[t + s]);
        __syncthreads();
    }
    float m = sdata[0];
    __syncthreads();

    float e = (t < P_) ? expf(v - m) : 0.0f;
    sdata[t] = e;
    __syncthreads();
    for (int s = 128; s > 0; s >>= 1) {
        if (t < s) sdata[t] += sdata[t + s];
        __syncthreads();
    }
    float inv = 1.0f / sdata[0];
    if (t < P_) alpha_out[b * P_ + t] = e * inv;
}

// ---------------------------------------------------------------------------
// Stage 4: awe[b,e] = sum_p enc[b,p,e] * alpha[b,p]
// ---------------------------------------------------------------------------
__global__ void awe_kernel(const float* __restrict__ enc,
                           const float* __restrict__ alpha,
                           float* __restrict__ awe) {
    __shared__ float sa[P_];
    const int b = blockIdx.y;
    const int e = blockIdx.x * 256 + threadIdx.x;
    for (int i = threadIdx.x; i < P_; i += 256)
        sa[i] = alpha[b * P_ + i];
    __syncthreads();

    const float* base = enc + (size_t)b * P_ * E_ + e;
    float acc = 0.0f;
    #pragma unroll 4
    for (int p = 0; p < P_; p++)
        acc = fmaf(base[(size_t)p * E_], sa[p], acc);
    awe[b * E_ + e] = acc;
}

// ---------------------------------------------------------------------------
extern "C" void kernel_launch(void* const* d_in, const int* in_sizes, int n_in,
                              void* d_out, int out_size) {
    const float* enc   = (const float*)d_in[0];
    const float* dh    = (const float*)d_in[1];
    const float* Wenc  = (const float*)d_in[2];
    const float* benc  = (const float*)d_in[3];
    const float* Wdec  = (const float*)d_in[4];
    const float* bdec  = (const float*)d_in[5];
    const float* wfull = (const float*)d_in[6];
    // d_in[7] = b_full: softmax-invariant, dropped.

    float* awe   = (float*)d_out;
    float* alpha = (float*)d_out + (size_t)B_ * E_;

    static int smem_set = 0;
    if (!smem_set) {
        cudaFuncSetAttribute(main_gemm_h,
                             cudaFuncAttributeMaxDynamicSharedMemorySize,
                             SM_TOTAL);
        smem_set = 1;
    }

    transpose_kernel<<<dim3(E_ / 32, A_ / 32), dim3(32, 8)>>>(Wenc);
    att2_kernel<<<dim3(A_ / 128, B_ / 16), 256>>>(dh, Wdec, bdec);
    main_gemm_h<<<dim3(M_ / 128, 2), 512, SM_TOTAL>>>(enc, benc, wfull);
    softmax_kernel<<<B_, 256>>>(alpha);
    awe_kernel<<<dim3(E_ / 256, B_), 256>>>(enc, alpha, awe);
}